// round 14
// baseline (speedup 1.0000x reference)
#include <cuda_runtime.h>
#include <math.h>
#include <stdint.h>

// Problem constants
#define BATCH   16384
#define DIN     1024
#define DH      4096
#define NCLS    10
#define TAU_F   0.5f
#define T1_IT   3
#define T2_IT   3

#define BM 128
#define BN 128
#define NT2 64                      // per-warp (64-col) partial tiles per row
#define MBLK (BATCH / BM)           // 128 m-blocks

// GEMM pipeline: K chunks of 128 int8 (=128B rows), 3 segs (a1b1, a1b0, a0b1)
#define BKC     128
#define CH_SEG  (DIN / BKC)         // 8
#define NCHUNK  (3 * CH_SEG)        // 24
#define STG     3

// Dynamic SMEM layout (offsets from 1024-aligned base)
#define A_BYTES      16384          // 128 x 128 int8
#define B_BYTES      16384          // 128 x 128 int8
#define STAGE_BYTES  (A_BYTES + B_BYTES)          // 32768
#define OFF_STAGE(s) ((s) * STAGE_BYTES)
#define OFF_W2       (3 * STAGE_BYTES)            // 98304: 128*10 f32 = 5120
#define OFF_B1       (OFF_W2 + 5120)              // 128 f32 = 512
#define DSMEM_BYTES  (1024 + OFF_B1 + 1024)       // ~105 KB -> 2 CTAs/SM

#define QMAXF   16255.0f

#define SWZ(o) ((o) ^ (((o) >> 3) & 0x70))

// Static scratch (no allocations)
__device__ float g_absmax[4];
__device__ unsigned int g_cnt[MBLK];                         // m-block arrival counters
__device__ signed char g_Xa1[(size_t)BATCH * DIN];           // 16 MB
__device__ signed char g_Xa0[(size_t)BATCH * DIN];           // 16 MB
__device__ signed char g_Wb1[2][(size_t)DH * DIN];           // 2 x 4 MB (K-major [N][K])
__device__ signed char g_Wb0[2][(size_t)DH * DIN];           // 2 x 4 MB
__device__ float g_P[2][(size_t)BATCH * NT2 * NCLS];         // 84 MB partial logits

// ---------------------------------------------------------------------------
// helpers
// ---------------------------------------------------------------------------
__device__ __forceinline__ uint32_t smem_u32(const void* p) {
    uint32_t a;
    asm("{ .reg .u64 t; cvta.to.shared.u64 t, %1; cvt.u32.u64 %0, t; }"
        : "=r"(a) : "l"(p));
    return a;
}

__device__ __forceinline__ void cp_async16(uint32_t dst, const void* src) {
    asm volatile("cp.async.cg.shared.global [%0], [%1], 16;" :: "r"(dst), "l"(src));
}
#define CP_COMMIT() asm volatile("cp.async.commit_group;" ::: "memory")
#define CP_WAIT1()  asm volatile("cp.async.wait_group 1;" ::: "memory")

__device__ __forceinline__ void ldsm_x4(uint32_t& r0, uint32_t& r1,
                                        uint32_t& r2, uint32_t& r3, uint32_t a) {
    asm volatile("ldmatrix.sync.aligned.m8n8.x4.shared.b16 {%0,%1,%2,%3}, [%4];"
                 : "=r"(r0), "=r"(r1), "=r"(r2), "=r"(r3) : "r"(a));
}

__device__ __forceinline__ void mma_s8(int& c0, int& c1, int& c2, int& c3,
                                       uint32_t a0, uint32_t a1, uint32_t a2, uint32_t a3,
                                       uint32_t b0, uint32_t b1) {
    asm volatile("mma.sync.aligned.m16n8k32.row.col.s32.s8.s8.s32 "
                 "{%0,%1,%2,%3}, {%4,%5,%6,%7}, {%8,%9}, {%0,%1,%2,%3};"
                 : "+r"(c0), "+r"(c1), "+r"(c2), "+r"(c3)
                 : "r"(a0), "r"(a1), "r"(a2), "r"(a3), "r"(b0), "r"(b1));
}

// q in [-16255, 16255] -> a1 in [-127,127], a0 in [-64,63], q = a1*128 + a0
__device__ __forceinline__ void quant2(float x, float invs,
                                       signed char& a1, signed char& a0) {
    int q = (int)rintf(x * invs);
    int hi = (q + 64) >> 7;
    a1 = (signed char)hi;
    a0 = (signed char)(q - (hi << 7));
}

__device__ __forceinline__ float inv_apprx_dev(float x, float m)
{
    float a = 2.f - (2.f / m) * x;
    float b = 1.f - (2.f / m) * x;
#pragma unroll
    for (int i = 0; i < T2_IT; i++) { b = b * b; a = a * (1.f + b); }
    return (2.f / m) * a;
}

__device__ __forceinline__ void softmax10(const float* z, float* p)
{
    float mx = z[0];
#pragma unroll
    for (int c = 1; c < NCLS; c++) mx = fmaxf(mx, z[c]);
    float s = 0.f;
#pragma unroll
    for (int c = 0; c < NCLS; c++) { p[c] = expf(z[c] - mx); s += p[c]; }
    float inv = 1.f / s;
#pragma unroll
    for (int c = 0; c < NCLS; c++) p[c] *= inv;
}

// ---------------------------------------------------------------------------
// Init: zero scales + arrival counters (every invocation -> graph-replay safe)
// ---------------------------------------------------------------------------
__global__ void init_kernel()
{
    if (threadIdx.x < 4) g_absmax[threadIdx.x] = 0.f;
    if (threadIdx.x < MBLK) g_cnt[threadIdx.x] = 0u;
}

// ---------------------------------------------------------------------------
// Fused absmax over {X, W1o, W1f}; slot = blockIdx.y
// ---------------------------------------------------------------------------
__global__ void absmax_kernel(const float* __restrict__ x,
                              const float* __restrict__ w1o,
                              const float* __restrict__ w1f)
{
    __shared__ float red[8];
    const int slot = blockIdx.y;
    const float* p = (slot == 0) ? x : (slot == 1) ? w1o : w1f;
    const int n4  = (slot == 0) ? BATCH * DIN / 4 : DIN * DH / 4;

    float m = 0.f;
    for (int i = blockIdx.x * blockDim.x + threadIdx.x; i < n4;
         i += gridDim.x * blockDim.x) {
        float4 v = ((const float4*)p)[i];
        m = fmaxf(m, fmaxf(fmaxf(fabsf(v.x), fabsf(v.y)),
                           fmaxf(fabsf(v.z), fabsf(v.w))));
    }
#pragma unroll
    for (int off = 16; off; off >>= 1)
        m = fmaxf(m, __shfl_xor_sync(0xffffffffu, m, off));
    if ((threadIdx.x & 31) == 0) red[threadIdx.x >> 5] = m;
    __syncthreads();
    if (threadIdx.x < 8) {
        m = red[threadIdx.x];
#pragma unroll
        for (int off = 4; off; off >>= 1)
            m = fmaxf(m, __shfl_xor_sync(0xffu, m, off));
        if (threadIdx.x == 0)
            atomicMax((int*)&g_absmax[slot], __float_as_int(m));
    }
}

// ---------------------------------------------------------------------------
// Quantize X -> int8 limbs
// ---------------------------------------------------------------------------
__global__ void qx_kernel(const float* __restrict__ X)
{
    int i = blockIdx.x * blockDim.x + threadIdx.x;       // float4 index
    float invs = QMAXF / fmaxf(g_absmax[0], 1e-30f);
    float4 v = ((const float4*)X)[i];
    char4 h, l;
    quant2(v.x, invs, h.x, l.x);
    quant2(v.y, invs, h.y, l.y);
    quant2(v.z, invs, h.z, l.z);
    quant2(v.w, invs, h.w, l.w);
    ((char4*)g_Xa1)[i] = h;
    ((char4*)g_Xa0)[i] = l;
}

// ---------------------------------------------------------------------------
// Quantize + transpose W1 [K,N] -> [N,K] int8 limbs; net = blockIdx.z
// ---------------------------------------------------------------------------
__global__ void qw_kernel(const float* __restrict__ W1o,
                          const float* __restrict__ W1f)
{
    __shared__ signed char t1[32][33], t0[32][33];
    const int net = blockIdx.z;
    const float* __restrict__ W = net ? W1f : W1o;
    float invs = QMAXF / fmaxf(g_absmax[1 + net], 1e-30f);
    int tx = threadIdx.x, ty = threadIdx.y;              // (32, 8)
    int n  = blockIdx.x * 32 + tx;
    int k0 = blockIdx.y * 32;
#pragma unroll
    for (int i = 0; i < 32; i += 8) {
        float v = W[(size_t)(k0 + ty + i) * DH + n];
        quant2(v, invs, t1[ty + i][tx], t0[ty + i][tx]);
    }
    __syncthreads();
    int kk = k0 + tx;
    int nn = blockIdx.x * 32 + ty;
    signed char* T1 = g_Wb1[net];
    signed char* T0 = g_Wb0[net];
#pragma unroll
    for (int i = 0; i < 32; i += 8) {
        T1[(size_t)(nn + i) * DIN + kk] = t1[tx][ty + i];
        T0[(size_t)(nn + i) * DIN + kk] = t0[tx][ty + i];
    }
}

// ---------------------------------------------------------------------------
// Main GEMM + fully fused head.  128x128 CTA tile, 4 warps of 64x64,
// 2 CTAs/SM, int8 2-limb merged-acc, cp.async 3-stage pipeline,
// register-direct partial-logit epilogue -> g_P, then the LAST of the 64
// CTAs per m-block (32 n-tiles x 2 nets) reduces partials in fixed order and
// writes the final blended output (deterministic).
// ---------------------------------------------------------------------------
__global__ __launch_bounds__(128, 2)
void gemm_s8_kernel(const float* __restrict__ b1o, const float* __restrict__ W2o,
                    const float* __restrict__ b1f, const float* __restrict__ W2f,
                    const float* __restrict__ b2o, const float* __restrict__ b2f,
                    float* __restrict__ out)
{
    extern __shared__ char dsm_raw[];
    __shared__ unsigned int s_last;
    const uint32_t raw  = smem_u32(dsm_raw);
    const uint32_t base = (raw + 1023) & ~1023u;
    char* gbase = dsm_raw + (base - raw);

    const int tid  = threadIdx.x;
    const int lane = tid & 31;
    const int wid  = tid >> 5;
    const int wm   = wid & 1;            // 2 warps over M (64 rows each)
    const int wn   = wid >> 1;           // 2 warps over N (64 cols each)
    const int m0   = blockIdx.y * BM;
    const int n0   = blockIdx.x * BN;
    const int net  = blockIdx.z;

    const float* __restrict__ b1 = net ? b1f : b1o;
    const float* __restrict__ W2 = net ? W2f : W2o;

    const signed char* __restrict__ Xa1 = g_Xa1;
    const signed char* __restrict__ Xa0 = g_Xa0;
    const signed char* __restrict__ Wb1 = g_Wb1[net];
    const signed char* __restrict__ Wb0 = g_Wb0[net];

    // epilogue constants (region disjoint from stages)
    float* W2s = (float*)(gbase + OFF_W2);
    float* b1s = (float*)(gbase + OFF_B1);
    for (int i = tid; i < BN * NCLS; i += 128)
        W2s[i] = W2[(size_t)(n0 + i / NCLS) * NCLS + (i % NCLS)];
    b1s[tid] = b1[n0 + tid];

    int acc[4][8][4];
#pragma unroll
    for (int i = 0; i < 4; i++)
#pragma unroll
        for (int j = 0; j < 8; j++)
#pragma unroll
            for (int r = 0; r < 4; r++) acc[i][j][r] = 0;

    auto produce = [&](int cc) {
        const int seg = cc / CH_SEG;
        const int kc  = (cc % CH_SEG) * BKC;
        const signed char* As = (seg < 2) ? Xa1 : Xa0;
        const signed char* Bs = (seg == 1) ? Wb0 : Wb1;
        const uint32_t st = base + OFF_STAGE(cc % STG);
#pragma unroll
        for (int i = 0; i < 8; i++) {              // A: 1024 x 16B / 128 thr
            int q = i * 128 + tid;
            int row = q >> 3, g = q & 7;
            cp_async16(st + SWZ(row * 128 + g * 16),
                       As + (size_t)(m0 + row) * DIN + kc + g * 16);
        }
#pragma unroll
        for (int i = 0; i < 8; i++) {              // B: 1024 x 16B / 128 thr
            int q = i * 128 + tid;
            int row = q >> 3, g = q & 7;
            cp_async16(st + A_BYTES + SWZ(row * 128 + g * 16),
                       Bs + (size_t)(n0 + row) * DIN + kc + g * 16);
        }
    };

    produce(0); CP_COMMIT();
    produce(1); CP_COMMIT();

    const int lrow = lane & 7;
    const int lsel = lane >> 3;                    // 0..3

    auto chunk_body = [&](int c) {
        CP_WAIT1();                                 // chunk c landed (c+1 may pend)
        __syncthreads();                            // all warps done with chunk c-1
        if (c + 2 < NCHUNK) produce(c + 2);
        CP_COMMIT();

        const uint32_t stA = base + OFF_STAGE(c % STG);
        const uint32_t stB = stA + A_BYTES;

#pragma unroll
        for (int ks = 0; ks < 4; ks++) {            // 4 x k32 per 128-K chunk
            const int kb = ks * 32;                 // byte offset in row

            uint32_t a[4][4];
#pragma unroll
            for (int mt = 0; mt < 4; mt++) {
                int row = wm * 64 + mt * 16 + lrow + (lsel & 1) * 8;
                int kof = (lsel >> 1) * 16;
                ldsm_x4(a[mt][0], a[mt][1], a[mt][2], a[mt][3],
                        stA + SWZ(row * 128 + kb + kof));
            }
            uint32_t b[8][2];
#pragma unroll
            for (int np = 0; np < 4; np++) {        // 4 x4-loads -> 8 n-tiles
                int row = wn * 64 + np * 16 + lrow + (lsel >> 1) * 8;
                int kof = (lsel & 1) * 16;
                ldsm_x4(b[np * 2][0], b[np * 2][1], b[np * 2 + 1][0], b[np * 2 + 1][1],
                        stB + SWZ(row * 128 + kb + kof));
            }
#pragma unroll
            for (int mt = 0; mt < 4; mt++)
#pragma unroll
                for (int nt = 0; nt < 8; nt++)
                    mma_s8(acc[mt][nt][0], acc[mt][nt][1],
                           acc[mt][nt][2], acc[mt][nt][3],
                           a[mt][0], a[mt][1], a[mt][2], a[mt][3],
                           b[nt][0], b[nt][1]);
        }
    };

    // seg0: a1*b1 chunks
    for (int c = 0; c < CH_SEG; c++) chunk_body(c);

    // scale acc by 128 once: cross terms (scale 2^7) accumulate in-place.
    // Bound: 128*1024*127^2 + 2*1024*127*64 = 2.131e9 < 2^31.  Exact.
#pragma unroll
    for (int i = 0; i < 4; i++)
#pragma unroll
        for (int j = 0; j < 8; j++)
#pragma unroll
            for (int r = 0; r < 4; r++) acc[i][j][r] <<= 7;

    // cross segs: a1*b0, a0*b1
    for (int c = CH_SEG; c < NCHUNK; c++) chunk_body(c);

    // ---- register-direct epilogue: dequant + bias + ReLU + W2 partials.
    const float suni = 128.f * (g_absmax[0] / QMAXF) * (g_absmax[1 + net] / QMAXF);
    const int col0g = wn * 64 + (lane & 3) * 2;     // + nt*8
    const int ntile = blockIdx.x * 2 + wn;
    float* P = g_P[net];

#pragma unroll
    for (int pass = 0; pass < 2; pass++) {
        const int cbase = pass * 5;
        float pl[4][2][5];
#pragma unroll
        for (int mt = 0; mt < 4; mt++)
#pragma unroll
            for (int hf = 0; hf < 2; hf++)
#pragma unroll
                for (int cc = 0; cc < 5; cc++) pl[mt][hf][cc] = 0.f;

#pragma unroll
        for (int nt = 0; nt < 8; nt++) {
            const int col0 = col0g + nt * 8;
            const float bc0 = b1s[col0], bc1 = b1s[col0 + 1];
            float w0[5], w1[5];
#pragma unroll
            for (int cc = 0; cc < 5; cc++) {
                w0[cc] = W2s[col0 * NCLS + cbase + cc];
                w1[cc] = W2s[(col0 + 1) * NCLS + cbase + cc];
            }
#pragma unroll
            for (int mt = 0; mt < 4; mt++) {
                float h0 = fmaxf(fmaf((float)acc[mt][nt][0], suni, bc0), 0.f);
                float h1 = fmaxf(fmaf((float)acc[mt][nt][1], suni, bc1), 0.f);
                float h2 = fmaxf(fmaf((float)acc[mt][nt][2], suni, bc0), 0.f);
                float h3 = fmaxf(fmaf((float)acc[mt][nt][3], suni, bc1), 0.f);
#pragma unroll
                for (int cc = 0; cc < 5; cc++) {
                    pl[mt][0][cc] = fmaf(h0, w0[cc], fmaf(h1, w1[cc], pl[mt][0][cc]));
                    pl[mt][1][cc] = fmaf(h2, w0[cc], fmaf(h3, w1[cc], pl[mt][1][cc]));
                }
            }
        }
#pragma unroll
        for (int mt = 0; mt < 4; mt++)
#pragma unroll
            for (int hf = 0; hf < 2; hf++) {
#pragma unroll
                for (int cc = 0; cc < 5; cc++) {
                    float v = pl[mt][hf][cc];
                    v += __shfl_xor_sync(0xffffffffu, v, 1);
                    v += __shfl_xor_sync(0xffffffffu, v, 2);
                    pl[mt][hf][cc] = v;
                }
                if ((lane & 3) == 0) {
                    int row = m0 + wm * 64 + mt * 16 + (lane >> 2) + hf * 8;
                    size_t pb = ((size_t)row * NT2 + ntile) * NCLS + cbase;
#pragma unroll
                    for (int cc = 0; cc < 5; cc++) P[pb + cc] = pl[mt][hf][cc];
                }
            }
    }

    // ---- last-CTA-per-m-block final reduction (threadFenceReduction pattern)
    __threadfence();                                // make P stores visible
    __syncthreads();
    if (tid == 0) {
        unsigned int old = atomicAdd(&g_cnt[blockIdx.y], 1u);
        s_last = (old == 63u) ? 1u : 0u;            // 32 tiles x 2 nets = 64
    }
    __syncthreads();

    if (s_last) {
        __threadfence();                            // acquire other CTAs' P stores
        const int row = m0 + tid;                   // one row per thread
        float zo[NCLS], zf[NCLS];
#pragma unroll
        for (int c = 0; c < NCLS; c++) { zo[c] = 0.f; zf[c] = 0.f; }

        const float2* po = (const float2*)(g_P[0] + (size_t)row * NT2 * NCLS);
        const float2* pf = (const float2*)(g_P[1] + (size_t)row * NT2 * NCLS);
        for (int t = 0; t < NT2; t++) {             // fixed order -> deterministic
#pragma unroll
            for (int p5 = 0; p5 < 5; p5++) {
                float2 vo = po[t * 5 + p5];
                float2 vf = pf[t * 5 + p5];
                zo[2 * p5]     += vo.x; zo[2 * p5 + 1] += vo.y;
                zf[2 * p5]     += vf.x; zf[2 * p5 + 1] += vf.y;
            }
        }

        float lo[NCLS], lf[NCLS], pso[NCLS], psf[NCLS];
#pragma unroll
        for (int c = 0; c < NCLS; c++) { lo[c] = zo[c] + b2o[c]; lf[c] = zf[c] + b2f[c]; }
        softmax10(lo, pso);
        softmax10(lf, psf);

        float res[NCLS + 1];
#pragma unroll
        for (int c = 0; c < NCLS; c++) res[c] = pso[c];
        res[NCLS] = TAU_F;
#pragma unroll
        for (int i = 0; i < T1_IT; i++) {
            float s = 0.f;
#pragma unroll
            for (int j = 0; j < NCLS + 1; j++) { res[j] = res[j] * res[j]; s += res[j]; }
            float m = (i == 0) ? (2.f + TAU_F * TAU_F) : 2.f;
            float inv = inv_apprx_dev(s, m);
#pragma unroll
            for (int j = 0; j < NCLS + 1; j++) res[j] *= inv;
        }
        float cond = res[NCLS];

        float* o = out + (size_t)row * NCLS;
#pragma unroll
        for (int c = 0; c < NCLS; c++)
            o[c] = pso[c] * (1.f - cond) + psf[c] * cond;
    }
}

// ---------------------------------------------------------------------------
// kernel_launch
// ---------------------------------------------------------------------------
extern "C" void kernel_launch(void* const* d_in, const int* in_sizes, int n_in,
                              void* d_out, int out_size)
{
    const float* x   = (const float*)d_in[0];
    const float* W1o = (const float*)d_in[1];
    const float* b1o = (const float*)d_in[2];
    const float* W2o = (const float*)d_in[3];
    const float* b2o = (const float*)d_in[4];
    const float* W1f = (const float*)d_in[5];
    const float* b1f = (const float*)d_in[6];
    const float* W2f = (const float*)d_in[7];
    const float* b2f = (const float*)d_in[8];
    float* out = (float*)d_out;

    cudaFuncSetAttribute(gemm_s8_kernel,
                         cudaFuncAttributeMaxDynamicSharedMemorySize, DSMEM_BYTES);

    init_kernel<<<1, 160>>>();
    absmax_kernel<<<dim3(1024, 3), 256>>>(x, W1o, W1f);
    qx_kernel<<<(BATCH * DIN / 4) / 256, 256>>>(x);
    qw_kernel<<<dim3(DH / 32, DIN / 32, 2), dim3(32, 8)>>>(W1o, W1f);

    dim3 ggrid(DH / BN, BATCH / BM, 2);   // (32, 128, 2)
    gemm_s8_kernel<<<ggrid, 128, DSMEM_BYTES>>>(b1o, W2o, b1f, W2f,
                                                b2o, b2f, out);
}

// round 15
// speedup vs baseline: 1.1520x; 1.1520x over previous
#include <cuda_runtime.h>
#include <math.h>
#include <stdint.h>

// Problem constants
#define BATCH   16384
#define DIN     1024
#define DH      4096
#define NCLS    10
#define TAU_F   0.5f
#define T1_IT   3
#define T2_IT   3

#define BM 128
#define BN 128
#define NT2 64                      // per-warp (64-col) partial tiles per row

// GEMM pipeline: K chunks of 128 int8 (=128B rows), 3 segs (a1b1, a1b0, a0b1)
#define BKC     128
#define CH_SEG  (DIN / BKC)         // 8
#define NCHUNK  (3 * CH_SEG)        // 24
#define STG     3

// Dynamic SMEM layout (offsets from 1024-aligned base)
#define A_BYTES      16384          // 128 x 128 int8
#define B_BYTES      16384          // 128 x 128 int8
#define STAGE_BYTES  (A_BYTES + B_BYTES)          // 32768
#define OFF_STAGE(s) ((s) * STAGE_BYTES)
#define OFF_W2       (3 * STAGE_BYTES)            // 98304: 128*10 f32 = 5120
#define OFF_B1       (OFF_W2 + 5120)              // 128 f32 = 512
#define DSMEM_BYTES  (1024 + OFF_B1 + 1024)       // ~105 KB -> 2 CTAs/SM

#define QMAXF   16255.0f

#define SWZ(o) ((o) ^ (((o) >> 3) & 0x70))

// Static scratch (no allocations)
__device__ float g_absmax[4];
__device__ signed char g_Xa1[(size_t)BATCH * DIN];           // 16 MB
__device__ signed char g_Xa0[(size_t)BATCH * DIN];           // 16 MB
__device__ signed char g_Wb1[2][(size_t)DH * DIN];           // 2 x 4 MB (K-major [N][K])
__device__ signed char g_Wb0[2][(size_t)DH * DIN];           // 2 x 4 MB
__device__ float g_P[2][(size_t)BATCH * NT2 * NCLS];         // 84 MB partial logits

// ---------------------------------------------------------------------------
// helpers
// ---------------------------------------------------------------------------
__device__ __forceinline__ uint32_t smem_u32(const void* p) {
    uint32_t a;
    asm("{ .reg .u64 t; cvta.to.shared.u64 t, %1; cvt.u32.u64 %0, t; }"
        : "=r"(a) : "l"(p));
    return a;
}

__device__ __forceinline__ void cp_async16(uint32_t dst, const void* src) {
    asm volatile("cp.async.cg.shared.global [%0], [%1], 16;" :: "r"(dst), "l"(src));
}
#define CP_COMMIT() asm volatile("cp.async.commit_group;" ::: "memory")
#define CP_WAIT1()  asm volatile("cp.async.wait_group 1;" ::: "memory")

__device__ __forceinline__ void ldsm_x4(uint32_t& r0, uint32_t& r1,
                                        uint32_t& r2, uint32_t& r3, uint32_t a) {
    asm volatile("ldmatrix.sync.aligned.m8n8.x4.shared.b16 {%0,%1,%2,%3}, [%4];"
                 : "=r"(r0), "=r"(r1), "=r"(r2), "=r"(r3) : "r"(a));
}

__device__ __forceinline__ void mma_s8(int& c0, int& c1, int& c2, int& c3,
                                       uint32_t a0, uint32_t a1, uint32_t a2, uint32_t a3,
                                       uint32_t b0, uint32_t b1) {
    asm volatile("mma.sync.aligned.m16n8k32.row.col.s32.s8.s8.s32 "
                 "{%0,%1,%2,%3}, {%4,%5,%6,%7}, {%8,%9}, {%0,%1,%2,%3};"
                 : "+r"(c0), "+r"(c1), "+r"(c2), "+r"(c3)
                 : "r"(a0), "r"(a1), "r"(a2), "r"(a3), "r"(b0), "r"(b1));
}

// q in [-16255, 16255] -> a1 in [-127,127], a0 in [-64,63], q = a1*128 + a0
__device__ __forceinline__ void quant2(float x, float invs,
                                       signed char& a1, signed char& a0) {
    int q = (int)rintf(x * invs);
    int hi = (q + 64) >> 7;
    a1 = (signed char)hi;
    a0 = (signed char)(q - (hi << 7));
}

__device__ __forceinline__ float inv_apprx_dev(float x, float m)
{
    float a = 2.f - (2.f / m) * x;
    float b = 1.f - (2.f / m) * x;
#pragma unroll
    for (int i = 0; i < T2_IT; i++) { b = b * b; a = a * (1.f + b); }
    return (2.f / m) * a;
}

__device__ __forceinline__ void softmax10(const float* z, float* p)
{
    float mx = z[0];
#pragma unroll
    for (int c = 1; c < NCLS; c++) mx = fmaxf(mx, z[c]);
    float s = 0.f;
#pragma unroll
    for (int c = 0; c < NCLS; c++) { p[c] = expf(z[c] - mx); s += p[c]; }
    float inv = 1.f / s;
#pragma unroll
    for (int c = 0; c < NCLS; c++) p[c] *= inv;
}

// ---------------------------------------------------------------------------
// Init: zero scales (every invocation -> graph-replay safe)
// ---------------------------------------------------------------------------
__global__ void init_kernel()
{
    if (threadIdx.x < 4) g_absmax[threadIdx.x] = 0.f;
}

// ---------------------------------------------------------------------------
// Fused absmax over {X, W1o, W1f}; slot = blockIdx.y
// ---------------------------------------------------------------------------
__global__ void absmax_kernel(const float* __restrict__ x,
                              const float* __restrict__ w1o,
                              const float* __restrict__ w1f)
{
    __shared__ float red[8];
    const int slot = blockIdx.y;
    const float* p = (slot == 0) ? x : (slot == 1) ? w1o : w1f;
    const int n4  = (slot == 0) ? BATCH * DIN / 4 : DIN * DH / 4;

    float m = 0.f;
    for (int i = blockIdx.x * blockDim.x + threadIdx.x; i < n4;
         i += gridDim.x * blockDim.x) {
        float4 v = ((const float4*)p)[i];
        m = fmaxf(m, fmaxf(fmaxf(fabsf(v.x), fabsf(v.y)),
                           fmaxf(fabsf(v.z), fabsf(v.w))));
    }
#pragma unroll
    for (int off = 16; off; off >>= 1)
        m = fmaxf(m, __shfl_xor_sync(0xffffffffu, m, off));
    if ((threadIdx.x & 31) == 0) red[threadIdx.x >> 5] = m;
    __syncthreads();
    if (threadIdx.x < 8) {
        m = red[threadIdx.x];
#pragma unroll
        for (int off = 4; off; off >>= 1)
            m = fmaxf(m, __shfl_xor_sync(0xffu, m, off));
        if (threadIdx.x == 0)
            atomicMax((int*)&g_absmax[slot], __float_as_int(m));
    }
}

// ---------------------------------------------------------------------------
// Quantize X -> int8 limbs
// ---------------------------------------------------------------------------
__global__ void qx_kernel(const float* __restrict__ X)
{
    int i = blockIdx.x * blockDim.x + threadIdx.x;       // float4 index
    float invs = QMAXF / fmaxf(g_absmax[0], 1e-30f);
    float4 v = ((const float4*)X)[i];
    char4 h, l;
    quant2(v.x, invs, h.x, l.x);
    quant2(v.y, invs, h.y, l.y);
    quant2(v.z, invs, h.z, l.z);
    quant2(v.w, invs, h.w, l.w);
    ((char4*)g_Xa1)[i] = h;
    ((char4*)g_Xa0)[i] = l;
}

// ---------------------------------------------------------------------------
// Quantize + transpose W1 [K,N] -> [N,K] int8 limbs; net = blockIdx.z
// ---------------------------------------------------------------------------
__global__ void qw_kernel(const float* __restrict__ W1o,
                          const float* __restrict__ W1f)
{
    __shared__ signed char t1[32][33], t0[32][33];
    const int net = blockIdx.z;
    const float* __restrict__ W = net ? W1f : W1o;
    float invs = QMAXF / fmaxf(g_absmax[1 + net], 1e-30f);
    int tx = threadIdx.x, ty = threadIdx.y;              // (32, 8)
    int n  = blockIdx.x * 32 + tx;
    int k0 = blockIdx.y * 32;
#pragma unroll
    for (int i = 0; i < 32; i += 8) {
        float v = W[(size_t)(k0 + ty + i) * DH + n];
        quant2(v, invs, t1[ty + i][tx], t0[ty + i][tx]);
    }
    __syncthreads();
    int kk = k0 + tx;
    int nn = blockIdx.x * 32 + ty;
    signed char* T1 = g_Wb1[net];
    signed char* T0 = g_Wb0[net];
#pragma unroll
    for (int i = 0; i < 32; i += 8) {
        T1[(size_t)(nn + i) * DIN + kk] = t1[tx][ty + i];
        T0[(size_t)(nn + i) * DIN + kk] = t0[tx][ty + i];
    }
}

// ---------------------------------------------------------------------------
// Main GEMM: 128x128 CTA tile, 4 warps (2x2) of 64x64, 128 threads, 2 CTAs/SM,
// int8 2-limb (3 passes, SINGLE merged s32 acc: acc <<= 7 after seg0),
// cp.async 3-stage pipeline, register-direct fused epilogue -> g_P (NT2=64).
// Both nets in one launch (blockIdx.z).
// ---------------------------------------------------------------------------
__global__ __launch_bounds__(128, 2)
void gemm_s8_kernel(const float* __restrict__ b1o, const float* __restrict__ W2o,
                    const float* __restrict__ b1f, const float* __restrict__ W2f)
{
    extern __shared__ char dsm_raw[];
    const uint32_t raw  = smem_u32(dsm_raw);
    const uint32_t base = (raw + 1023) & ~1023u;
    char* gbase = dsm_raw + (base - raw);

    const int tid  = threadIdx.x;
    const int wid  = tid >> 5;
    const int lane = tid & 31;
    const int wm   = wid & 1;            // 2 warps over M (64 rows each)
    const int wn   = wid >> 1;           // 2 warps over N (64 cols each)
    const int m0   = blockIdx.y * BM;
    const int n0   = blockIdx.x * BN;
    const int net  = blockIdx.z;

    const float* __restrict__ b1 = net ? b1f : b1o;
    const float* __restrict__ W2 = net ? W2f : W2o;

    const signed char* __restrict__ Xa1 = g_Xa1;
    const signed char* __restrict__ Xa0 = g_Xa0;
    const signed char* __restrict__ Wb1 = g_Wb1[net];
    const signed char* __restrict__ Wb0 = g_Wb0[net];

    // epilogue constants (region disjoint from stages)
    float* W2s = (float*)(gbase + OFF_W2);
    float* b1s = (float*)(gbase + OFF_B1);
    for (int i = tid; i < BN * NCLS; i += 128)
        W2s[i] = W2[(size_t)(n0 + i / NCLS) * NCLS + (i % NCLS)];
    b1s[tid] = b1[n0 + tid];

    int acc[4][8][4];
#pragma unroll
    for (int i = 0; i < 4; i++)
#pragma unroll
        for (int j = 0; j < 8; j++)
#pragma unroll
            for (int r = 0; r < 4; r++) acc[i][j][r] = 0;

    auto produce = [&](int cc) {
        const int seg = cc / CH_SEG;
        const int kc  = (cc % CH_SEG) * BKC;
        const signed char* As = (seg < 2) ? Xa1 : Xa0;
        const signed char* Bs = (seg == 1) ? Wb0 : Wb1;
        const uint32_t st = base + OFF_STAGE(cc % STG);
#pragma unroll
        for (int i = 0; i < 8; i++) {              // A: 1024 x 16B / 128 thr
            int q = i * 128 + tid;
            int row = q >> 3, g = q & 7;
            cp_async16(st + SWZ(row * 128 + g * 16),
                       As + (size_t)(m0 + row) * DIN + kc + g * 16);
        }
#pragma unroll
        for (int i = 0; i < 8; i++) {              // B: 1024 x 16B / 128 thr
            int q = i * 128 + tid;
            int row = q >> 3, g = q & 7;
            cp_async16(st + A_BYTES + SWZ(row * 128 + g * 16),
                       Bs + (size_t)(n0 + row) * DIN + kc + g * 16);
        }
    };

    produce(0); CP_COMMIT();
    produce(1); CP_COMMIT();

    const int lrow = lane & 7;
    const int lsel = lane >> 3;                    // 0..3

    auto chunk_body = [&](int c) {
        CP_WAIT1();                                 // chunk c landed (c+1 may pend)
        __syncthreads();                            // all warps done with chunk c-1
        if (c + 2 < NCHUNK) produce(c + 2);
        CP_COMMIT();

        const uint32_t stA = base + OFF_STAGE(c % STG);
        const uint32_t stB = stA + A_BYTES;

#pragma unroll
        for (int ks = 0; ks < 4; ks++) {            // 4 x k32 per 128-K chunk
            const int kb = ks * 32;                 // byte offset in row

            uint32_t a[4][4];
#pragma unroll
            for (int mt = 0; mt < 4; mt++) {
                int row = wm * 64 + mt * 16 + lrow + (lsel & 1) * 8;
                int kof = (lsel >> 1) * 16;
                ldsm_x4(a[mt][0], a[mt][1], a[mt][2], a[mt][3],
                        stA + SWZ(row * 128 + kb + kof));
            }
            uint32_t b[8][2];
#pragma unroll
            for (int np = 0; np < 4; np++) {        // 4 x4-loads -> 8 n-tiles
                int row = wn * 64 + np * 16 + lrow + (lsel >> 1) * 8;
                int kof = (lsel & 1) * 16;
                ldsm_x4(b[np * 2][0], b[np * 2][1], b[np * 2 + 1][0], b[np * 2 + 1][1],
                        stB + SWZ(row * 128 + kb + kof));
            }
#pragma unroll
            for (int mt = 0; mt < 4; mt++)
#pragma unroll
                for (int nt = 0; nt < 8; nt++)
                    mma_s8(acc[mt][nt][0], acc[mt][nt][1],
                           acc[mt][nt][2], acc[mt][nt][3],
                           a[mt][0], a[mt][1], a[mt][2], a[mt][3],
                           b[nt][0], b[nt][1]);
        }
    };

    // seg0: a1*b1 chunks
    for (int c = 0; c < CH_SEG; c++) chunk_body(c);

    // scale acc by 128 once: cross terms (scale 2^7) accumulate in-place.
    // Bound: 128*1024*127^2 + 2*1024*127*64 = 2.131e9 < 2^31.  Exact.
#pragma unroll
    for (int i = 0; i < 4; i++)
#pragma unroll
        for (int j = 0; j < 8; j++)
#pragma unroll
            for (int r = 0; r < 4; r++) acc[i][j][r] <<= 7;

    // cross segs: a1*b0, a0*b1
    for (int c = CH_SEG; c < NCHUNK; c++) chunk_body(c);

    // ---- register-direct epilogue: dequant + bias + ReLU + W2 partials.
    // h = acc * 128 * s_x * s_w; per-thread partial logits over its 16 cols,
    // quad shfl reduce -> per-warp 64-col partials -> g_P[net][row][ntile][c].
    const float suni = 128.f * (g_absmax[0] / QMAXF) * (g_absmax[1 + net] / QMAXF);
    const int col0g = wn * 64 + (lane & 3) * 2;     // + nt*8
    const int ntile = blockIdx.x * 2 + wn;
    float* P = g_P[net];

#pragma unroll
    for (int pass = 0; pass < 2; pass++) {
        const int cbase = pass * 5;
        float pl[4][2][5];
#pragma unroll
        for (int mt = 0; mt < 4; mt++)
#pragma unroll
            for (int hf = 0; hf < 2; hf++)
#pragma unroll
                for (int cc = 0; cc < 5; cc++) pl[mt][hf][cc] = 0.f;

#pragma unroll
        for (int nt = 0; nt < 8; nt++) {
            const int col0 = col0g + nt * 8;
            const float bc0 = b1s[col0], bc1 = b1s[col0 + 1];
            float w0[5], w1[5];
#pragma unroll
            for (int cc = 0; cc < 5; cc++) {
                w0[cc] = W2s[col0 * NCLS + cbase + cc];
                w1[cc] = W2s[(col0 + 1) * NCLS + cbase + cc];
            }
#pragma unroll
            for (int mt = 0; mt < 4; mt++) {
                float h0 = fmaxf(fmaf((float)acc[mt][nt][0], suni, bc0), 0.f);
                float h1 = fmaxf(fmaf((float)acc[mt][nt][1], suni, bc1), 0.f);
                float h2 = fmaxf(fmaf((float)acc[mt][nt][2], suni, bc0), 0.f);
                float h3 = fmaxf(fmaf((float)acc[mt][nt][3], suni, bc1), 0.f);
#pragma unroll
                for (int cc = 0; cc < 5; cc++) {
                    pl[mt][0][cc] = fmaf(h0, w0[cc], fmaf(h1, w1[cc], pl[mt][0][cc]));
                    pl[mt][1][cc] = fmaf(h2, w0[cc], fmaf(h3, w1[cc], pl[mt][1][cc]));
                }
            }
        }
        // reduce over the 4 lanes of each quad (lane&3), then lane&3==0 writes
#pragma unroll
        for (int mt = 0; mt < 4; mt++)
#pragma unroll
            for (int hf = 0; hf < 2; hf++) {
#pragma unroll
                for (int cc = 0; cc < 5; cc++) {
                    float v = pl[mt][hf][cc];
                    v += __shfl_xor_sync(0xffffffffu, v, 1);
                    v += __shfl_xor_sync(0xffffffffu, v, 2);
                    pl[mt][hf][cc] = v;
                }
                if ((lane & 3) == 0) {
                    int row = m0 + wm * 64 + mt * 16 + (lane >> 2) + hf * 8;
                    size_t pb = ((size_t)row * NT2 + ntile) * NCLS + cbase;
#pragma unroll
                    for (int cc = 0; cc < 5; cc++) P[pb + cc] = pl[mt][hf][cc];
                }
            }
    }
}

// ---------------------------------------------------------------------------
// Stage 2: reduce 64 partials/row (both nets), +b2, softmax, comp_max_tau, blend
// ---------------------------------------------------------------------------
__global__ __launch_bounds__(256)
void reduce_head_kernel(const float* __restrict__ b2o,
                        const float* __restrict__ b2f,
                        float* __restrict__ out)
{
    const int row  = (blockIdx.x * blockDim.x + threadIdx.x) >> 5;
    const int lane = threadIdx.x & 31;
    if (row >= BATCH) return;

    const float* po = g_P[0] + ((size_t)row * NT2 + lane) * NCLS;
    const float* pf = g_P[1] + ((size_t)row * NT2 + lane) * NCLS;
    const float* po2 = po + 32 * NCLS;
    const float* pf2 = pf + 32 * NCLS;

    float zo[NCLS], zf[NCLS];
#pragma unroll
    for (int p = 0; p < 5; p++) {
        float2 a = *(const float2*)(po + 2 * p);
        float2 b = *(const float2*)(po2 + 2 * p);
        zo[2 * p] = a.x + b.x; zo[2 * p + 1] = a.y + b.y;
        float2 cv = *(const float2*)(pf + 2 * p);
        float2 dv = *(const float2*)(pf2 + 2 * p);
        zf[2 * p] = cv.x + dv.x; zf[2 * p + 1] = cv.y + dv.y;
    }

#pragma unroll
    for (int c = 0; c < NCLS; c++) {
#pragma unroll
        for (int off = 16; off; off >>= 1) {
            zo[c] += __shfl_xor_sync(0xffffffffu, zo[c], off);
            zf[c] += __shfl_xor_sync(0xffffffffu, zf[c], off);
        }
    }

    if (lane == 0) {
        float lo[NCLS], lf[NCLS], pso[NCLS], psf[NCLS];
#pragma unroll
        for (int c = 0; c < NCLS; c++) { lo[c] = zo[c] + b2o[c]; lf[c] = zf[c] + b2f[c]; }
        softmax10(lo, pso);
        softmax10(lf, psf);

        float res[NCLS + 1];
#pragma unroll
        for (int c = 0; c < NCLS; c++) res[c] = pso[c];
        res[NCLS] = TAU_F;
#pragma unroll
        for (int i = 0; i < T1_IT; i++) {
            float s = 0.f;
#pragma unroll
            for (int j = 0; j < NCLS + 1; j++) { res[j] = res[j] * res[j]; s += res[j]; }
            float m = (i == 0) ? (2.f + TAU_F * TAU_F) : 2.f;
            float inv = inv_apprx_dev(s, m);
#pragma unroll
            for (int j = 0; j < NCLS + 1; j++) res[j] *= inv;
        }
        float cond = res[NCLS];

        float* o = out + (size_t)row * NCLS;
#pragma unroll
        for (int c = 0; c < NCLS; c++)
            o[c] = pso[c] * (1.f - cond) + psf[c] * cond;
    }
}

// ---------------------------------------------------------------------------
// kernel_launch
// ---------------------------------------------------------------------------
extern "C" void kernel_launch(void* const* d_in, const int* in_sizes, int n_in,
                              void* d_out, int out_size)
{
    const float* x   = (const float*)d_in[0];
    const float* W1o = (const float*)d_in[1];
    const float* b1o = (const float*)d_in[2];
    const float* W2o = (const float*)d_in[3];
    const float* b2o = (const float*)d_in[4];
    const float* W1f = (const float*)d_in[5];
    const float* b1f = (const float*)d_in[6];
    const float* W2f = (const float*)d_in[7];
    const float* b2f = (const float*)d_in[8];
    float* out = (float*)d_out;

    cudaFuncSetAttribute(gemm_s8_kernel,
                         cudaFuncAttributeMaxDynamicSharedMemorySize, DSMEM_BYTES);

    init_kernel<<<1, 32>>>();
    absmax_kernel<<<dim3(1024, 3), 256>>>(x, W1o, W1f);
    qx_kernel<<<(BATCH * DIN / 4) / 256, 256>>>(x);
    qw_kernel<<<dim3(DH / 32, DIN / 32, 2), dim3(32, 8)>>>(W1o, W1f);

    dim3 ggrid(DH / BN, BATCH / BM, 2);   // (32, 128, 2)
    gemm_s8_kernel<<<ggrid, 128, DSMEM_BYTES>>>(b1o, W2o, b1f, W2f);

    reduce_head_kernel<<<(BATCH * 32) / 256, 256>>>(b2o, b2f, out);
}